// round 15
// baseline (speedup 1.0000x reference)
#include <cuda_runtime.h>
#include <cuda_bf16.h>
#include <cstdint>

#define BATCH 8

// ---------------- scratch ----------------
__device__ float g_bufA[8u*64u*128u*128u];
__device__ float g_bufB[8u*64u*128u*128u];
__device__ __nv_bfloat16 g_colH[75497472u];   // [k][n] hi plane (max conv1_2: 576 x 131072)
__device__ __nv_bfloat16 g_colL[75497472u];
__device__ __nv_bfloat16 g_wH[14710784u];
__device__ __nv_bfloat16 g_wL[14710784u];
__device__ float g_part[4194304u];
__device__ int4   g_tabI[196416];
__device__ float4 g_tabW[196416];
__device__ float g_vec1[8*4096];
__device__ float g_vec2[8*4096];

#define TB128 0
#define TB64  147456
#define TB32  184320
#define TB16  193536
#define TB8   195840

// ---------------- PTX helpers (family-common sm_80+) ----------------
__device__ __forceinline__ uint32_t s2u(const void* p) {
    uint32_t a;
    asm("{ .reg .u64 t; cvta.to.shared.u64 t, %1; cvt.u32.u64 %0, t; }" : "=r"(a) : "l"(p));
    return a;
}
#define CPA(dst, src) asm volatile("cp.async.cg.shared.global [%0], [%1], 16;" :: "r"(dst), "l"(src))
#define CPA_COMMIT()  asm volatile("cp.async.commit_group;" ::: "memory")
#define CPA_WAIT0()   asm volatile("cp.async.wait_group 0;" ::: "memory")
#define LDM4(r, addr) asm volatile("ldmatrix.sync.aligned.m8n8.x4.shared.b16 {%0,%1,%2,%3}, [%4];" \
    : "=r"((r)[0]), "=r"((r)[1]), "=r"((r)[2]), "=r"((r)[3]) : "r"(addr))
#define LDM4T(r, addr) asm volatile("ldmatrix.sync.aligned.m8n8.x4.trans.shared.b16 {%0,%1,%2,%3}, [%4];" \
    : "=r"((r)[0]), "=r"((r)[1]), "=r"((r)[2]), "=r"((r)[3]) : "r"(addr))
#define MMA(d, a, b) asm volatile( \
    "mma.sync.aligned.m16n8k16.row.col.f32.bf16.bf16.f32 {%0,%1,%2,%3},{%4,%5,%6,%7},{%8,%9},{%0,%1,%2,%3};" \
    : "+f"((d)[0]), "+f"((d)[1]), "+f"((d)[2]), "+f"((d)[3]) \
    : "r"((a)[0]), "r"((a)[1]), "r"((a)[2]), "r"((a)[3]), "r"((b)[0]), "r"((b)[1]))

// ---------------- tab build ----------------
__device__ __forceinline__ void tab_one(int t, int H, int base) {
    int HW = H * H;
    if (t >= HW * 9) return;
    int k = t % 9, pos = t / 9;
    int y = pos / H, x = pos % H;

    float cc = 0.5f * (float)H - 0.5f;
    float th = atan2f((float)x - cc, (float)y - cc);
    if (th < 0.f) th += 6.28318530717958647692f;
    th = rintf(th * 10000.0f) / 10000.0f;

    int ky = k / 3, kx = k % 3;
    float offy = 0.f, offx = 0.f;
    if (k != 4) {
        int m = (k < 4) ? k : k - 1;
        float ang = th + (float)(3.14159265358979323846 * 0.25 * (double)m);
        offy = cosf(ang) + (float)(1 - ky);
        offx = sinf(ang) + (float)(1 - kx);
    }
    float py = (float)(y - 1 + ky) + offy;
    float px = (float)(x - 1 + kx) + offx;
    float y0 = floorf(py), x0 = floorf(px);
    float fy = py - y0, fx = px - x0;
    float Hm = (float)(H - 1);

    float ys[2] = {y0, y0 + 1.f};
    float xs[2] = {x0, x0 + 1.f};
    float wy[2] = {1.f - fy, fy};
    float wx[2] = {1.f - fx, fx};

    int ids[4]; float ws[4]; int q = 0;
    #pragma unroll
    for (int iy = 0; iy < 2; iy++) {
        #pragma unroll
        for (int ix = 0; ix < 2; ix++) {
            float yf = ys[iy], xf = xs[ix];
            bool v = (yf >= 0.f) && (yf <= Hm) && (xf >= 0.f) && (xf <= Hm);
            int yi = (int)fminf(fmaxf(yf, 0.f), Hm);
            int xi = (int)fminf(fmaxf(xf, 0.f), Hm);
            ids[q] = yi * H + xi;
            ws[q]  = v ? (wy[iy] * wx[ix]) : 0.f;
            q++;
        }
    }
    g_tabI[base + t] = make_int4(ids[0], ids[1], ids[2], ids[3]);
    g_tabW[base + t] = make_float4(ws[0], ws[1], ws[2], ws[3]);
}

__global__ void prep_all() {
    int b = blockIdx.x, t = threadIdx.x;
    if      (b < 576) tab_one((b      ) * 256 + t, 128, TB128);
    else if (b < 720) tab_one((b - 576) * 256 + t,  64, TB64);
    else if (b < 756) tab_one((b - 720) * 256 + t,  32, TB32);
    else if (b < 765) tab_one((b - 756) * 256 + t,  16, TB16);
    else              tab_one((b - 765) * 256 + t,   8, TB8);
}

// ---------------- all-layer weight conversion ----------------
struct WParams {
    const float* W[13];
    int O[13]; int Kreal[13]; int Kpad[13]; unsigned off[13];
};
__global__ void convW_all(WParams P, __nv_bfloat16* __restrict__ wH, __nv_bfloat16* __restrict__ wL) {
    int layer = blockIdx.y;
    int Kr = P.Kreal[layer], Kp = P.Kpad[layer];
    int total = P.O[layer] * Kp;
    const float* W = P.W[layer];
    unsigned off = P.off[layer];
    for (int t = blockIdx.x * 256 + threadIdx.x; t < total; t += gridDim.x * 256) {
        int o = t / Kp, k = t - o * Kp;
        float w = (k < Kr) ? W[(size_t)o * Kr + k] : 0.f;
        __nv_bfloat16 h = __float2bfloat16(w);
        wH[off + t] = h;
        wL[off + t] = __float2bfloat16(w - __bfloat162float(h));
    }
}

// ---------------- deformable im2col -> bf16 hi/lo, [k][n], channel-parallel ----------------
__global__ void im2col2(const float* __restrict__ x, __nv_bfloat16* __restrict__ colH,
                        __nv_bfloat16* __restrict__ colL, int Cin, int HW, int Ntot,
                        int tabBase, int CB) {
    int n = blockIdx.x * blockDim.x + threadIdx.x;
    int tap = blockIdx.y;
    int c0 = blockIdx.z * CB;
    int pos = n % HW, b = n / HW;
    int4   id = g_tabI[tabBase + pos * 9 + tap];
    float4 w  = g_tabW[tabBase + pos * 9 + tap];
    const float* xb = x + ((size_t)b * Cin + c0) * HW;
    size_t cstep = (size_t)9 * Ntot;
    __nv_bfloat16* pH = colH + ((size_t)c0 * 9 + tap) * Ntot + n;
    __nv_bfloat16* pL = colL + ((size_t)c0 * 9 + tap) * Ntot + n;
    for (int c = 0; c < CB; c++) {
        const float* xc = xb + (size_t)c * HW;
        float v = xc[id.x] * w.x + xc[id.y] * w.y + xc[id.z] * w.z + xc[id.w] * w.w;
        __nv_bfloat16 h = __float2bfloat16(v);
        pH[c * cstep] = h;
        pL[c * cstep] = __float2bfloat16(v - __bfloat162float(h));
    }
}

// ---------------- HMMA GEMM 256x64x32, 2 CTAs/SM, optional fused ReLU+maxpool ----------------
#define RSA 264
#define RSB 40
#define OF_AL 16896
#define OF_B  33792
#define OF_BL 5120
#define STAGE_B 44032
#define SMEM_TOT 88064
#define PRS 66            // pooled-epilogue staging row stride (floats)
__global__ void __launch_bounds__(256, 2) gemm_mma(
    const __nv_bfloat16* __restrict__ AH, const __nv_bfloat16* __restrict__ AL,
    const __nv_bfloat16* __restrict__ WH, const __nv_bfloat16* __restrict__ WL,
    float* __restrict__ out, float* __restrict__ part,
    int Ntot, int Kpad, int chunkK, int Cout, int HW, int H, int doPool) {
    extern __shared__ char smem[];
    uint32_t sb0 = s2u(smem);
    int tid = threadIdx.x, l = tid & 31, wid = tid >> 5;
    int wm = wid & 3, wn = wid >> 2;
    int bn = blockIdx.x * 256, bo = blockIdx.y * 64;
    int kStart = blockIdx.z * chunkK;
    int nk = chunkK >> 5;

    float acc[4][4][4];
    #pragma unroll
    for (int i = 0; i < 4; i++)
        #pragma unroll
        for (int j = 0; j < 4; j++)
            #pragma unroll
            for (int q = 0; q < 4; q++) acc[i][j][q] = 0.f;

    auto load_stage = [&](int st, int k0) {
        uint32_t sb = sb0 + st * STAGE_B;
        #pragma unroll
        for (int i = 0; i < 8; i++) {
            int u = tid + i * 256;
            int plane = u >> 10, rem = u & 1023;
            int krow = rem >> 5, c = rem & 31;
            const __nv_bfloat16* src = (plane ? AL : AH) + (size_t)(k0 + krow) * Ntot + bn + c * 8;
            uint32_t dst = sb + plane * OF_AL + (uint32_t)(krow * RSA + c * 8) * 2;
            CPA(dst, src);
        }
        #pragma unroll
        for (int i = 0; i < 2; i++) {
            int u = tid + i * 256;
            int plane = u >> 8, rem = u & 255;
            int row = rem >> 2, c = rem & 3;
            const __nv_bfloat16* src = (plane ? WL : WH) + (size_t)(bo + row) * Kpad + k0 + c * 8;
            uint32_t dst = sb + OF_B + plane * OF_BL + (uint32_t)(row * RSB + c * 8) * 2;
            CPA(dst, src);
        }
        CPA_COMMIT();
    };

    load_stage(0, kStart);

    int krow = (l & 7) + ((l & 16) >> 1);
    int mcol = (l & 8);
    int browB = (l & 7) + ((l >> 4) << 3);
    int bcol  = ((l >> 3) & 1) * 8;

    for (int it = 0; it < nk; it++) {
        CPA_WAIT0();
        __syncthreads();
        if (it + 1 < nk) load_stage((it + 1) & 1, kStart + (it + 1) * 32);

        uint32_t base = sb0 + (it & 1) * STAGE_B;
        #pragma unroll
        for (int ks = 0; ks < 2; ks++) {
            uint32_t aH[4][4], aL[4][4], bH[4][2], bL[4][2];
            #pragma unroll
            for (int mi = 0; mi < 4; mi++) {
                uint32_t off = (uint32_t)((ks * 16 + krow) * RSA + wm * 64 + mi * 16 + mcol) * 2;
                LDM4T(aH[mi], base + off);
                LDM4T(aL[mi], base + OF_AL + off);
            }
            #pragma unroll
            for (int j = 0; j < 2; j++) {
                int row = wn * 32 + j * 16 + browB;
                uint32_t off = OF_B + (uint32_t)(row * RSB + ks * 16 + bcol) * 2;
                uint32_t r[4];
                LDM4(r, base + off);
                bH[2*j][0] = r[0]; bH[2*j][1] = r[1]; bH[2*j+1][0] = r[2]; bH[2*j+1][1] = r[3];
                LDM4(r, base + off + OF_BL);
                bL[2*j][0] = r[0]; bL[2*j][1] = r[1]; bL[2*j+1][0] = r[2]; bL[2*j+1][1] = r[3];
            }
            #pragma unroll
            for (int mi = 0; mi < 4; mi++)
                #pragma unroll
                for (int nf = 0; nf < 4; nf++) {
                    MMA(acc[mi][nf], aH[mi], bH[nf]);
                    MMA(acc[mi][nf], aH[mi], bL[nf]);
                    MMA(acc[mi][nf], aL[mi], bH[nf]);
                }
        }
        __syncthreads();
    }

    if (doPool) {
        // stage full 256x64 tile in smem, then 2x2 maxpool + ReLU, coalesced pooled store
        float* st = (float*)smem;
        #pragma unroll
        for (int mi = 0; mi < 4; mi++)
            #pragma unroll
            for (int nf = 0; nf < 4; nf++) {
                int pl = wm * 64 + mi * 16 + (l >> 2);
                int cl = wn * 32 + nf * 8 + 2 * (l & 3);
                float* d = acc[mi][nf];
                st[pl * PRS + cl]           = d[0];
                st[pl * PRS + cl + 1]       = d[1];
                st[(pl + 8) * PRS + cl]     = d[2];
                st[(pl + 8) * PRS + cl + 1] = d[3];
            }
        __syncthreads();
        int b0 = bn / HW;
        int HWo = HW >> 2, Ho2 = H >> 1;
        int pbase = (bn % HW) >> 2;
        #pragma unroll
        for (int i = 0; i < 16; i++) {
            int v = tid + i * 256;
            int col = v >> 6, pp = v & 63;
            int yp = pp / Ho2, xp = pp - yp * Ho2;
            int pl = 2 * yp * H + 2 * xp;
            float m = fmaxf(fmaxf(st[pl * PRS + col], st[(pl + 1) * PRS + col]),
                            fmaxf(st[(pl + H) * PRS + col], st[(pl + H + 1) * PRS + col]));
            out[((size_t)b0 * Cout + bo + col) * HWo + pbase + pp] = fmaxf(m, 0.f);
        }
        return;
    }

    bool dosplit = (gridDim.z > 1);
    #pragma unroll
    for (int mi = 0; mi < 4; mi++)
        #pragma unroll
        for (int nf = 0; nf < 4; nf++) {
            int row0 = bn + wm * 64 + mi * 16 + (l >> 2);
            int col0 = bo + wn * 32 + nf * 8 + 2 * (l & 3);
            float* d = acc[mi][nf];
            if (dosplit) {
                size_t zb = (size_t)blockIdx.z * Cout;
                part[(zb + col0)     * Ntot + row0]     = d[0];
                part[(zb + col0 + 1) * Ntot + row0]     = d[1];
                part[(zb + col0)     * Ntot + row0 + 8] = d[2];
                part[(zb + col0 + 1) * Ntot + row0 + 8] = d[3];
            } else {
                int b0 = row0 / HW, p0 = row0 % HW;
                int r1 = row0 + 8;
                int b1 = r1 / HW, p1 = r1 % HW;
                out[((size_t)b0 * Cout + col0)     * HW + p0] = fmaxf(d[0], 0.f);
                out[((size_t)b0 * Cout + col0 + 1) * HW + p0] = fmaxf(d[1], 0.f);
                out[((size_t)b1 * Cout + col0)     * HW + p1] = fmaxf(d[2], 0.f);
                out[((size_t)b1 * Cout + col0 + 1) * HW + p1] = fmaxf(d[3], 0.f);
            }
        }
}

// ---------------- split-K reduce + ReLU (optional fused maxpool) ----------------
__global__ void reduceK(const float* __restrict__ part, float* __restrict__ out,
                        int Cout, int N, int HW, int H, int nslab, int doPool) {
    int t = blockIdx.x * blockDim.x + threadIdx.x;
    if (!doPool) {
        if (t >= Cout * N) return;
        int o = t / N, n = t % N;
        float s = 0.f;
        for (int z = 0; z < nslab; z++)
            s += part[((size_t)z * Cout + o) * N + n];
        int b = n / HW, pos = n % HW;
        out[((size_t)b * Cout + o) * HW + pos] = fmaxf(s, 0.f);
    } else {
        int N4 = N >> 2;
        if (t >= Cout * N4) return;
        int o = t / N4, r = t - o * N4;
        int HWo = HW >> 2, Ho2 = H >> 1;
        int b = r / HWo, pp = r - b * HWo;
        int yp = pp / Ho2, xp = pp - yp * Ho2;
        int n00 = b * HW + 2 * yp * H + 2 * xp;
        float s00 = 0.f, s01 = 0.f, s10 = 0.f, s11 = 0.f;
        for (int z = 0; z < nslab; z++) {
            const float* p = part + ((size_t)z * Cout + o) * N + n00;
            s00 += p[0]; s01 += p[1]; s10 += p[H]; s11 += p[H + 1];
        }
        float m = fmaxf(fmaxf(s00, s01), fmaxf(s10, s11));
        out[((size_t)b * Cout + o) * HWo + pp] = fmaxf(m, 0.f);
    }
}

// ---------------- avgpool / FC ----------------
__global__ void avgpool4(const float* __restrict__ in, float* __restrict__ out) {
    int t = blockIdx.x * blockDim.x + threadIdx.x;
    if (t >= BATCH * 512) return;
    const float* p = in + (size_t)t * 16;
    float s = 0.f;
    #pragma unroll
    for (int i = 0; i < 16; i++) s += p[i];
    out[t] = s * (1.f / 16.f);
}

__global__ void fc_kernel(const float* __restrict__ v, const float* __restrict__ Wf,
                          const float* __restrict__ bias, float* __restrict__ out,
                          int In, int Out, int doRelu) {
    int warp = (blockIdx.x * blockDim.x + threadIdx.x) >> 5;
    int lane = threadIdx.x & 31;
    if (warp >= Out) return;
    const float* wrow = Wf + (size_t)warp * In;
    float acc[BATCH];
    #pragma unroll
    for (int b = 0; b < BATCH; b++) acc[b] = 0.f;
    for (int i = lane; i < In; i += 32) {
        float wv = wrow[i];
        #pragma unroll
        for (int b = 0; b < BATCH; b++)
            acc[b] = fmaf(wv, v[b * In + i], acc[b]);
    }
    #pragma unroll
    for (int b = 0; b < BATCH; b++) {
        #pragma unroll
        for (int off = 16; off; off >>= 1)
            acc[b] += __shfl_xor_sync(0xffffffffu, acc[b], off);
    }
    if (lane == 0) {
        float bi = bias[warp];
        #pragma unroll
        for (int b = 0; b < BATCH; b++) {
            float r = acc[b] + bi;
            if (doRelu) r = fmaxf(r, 0.f);
            out[b * Out + warp] = r;
        }
    }
}

// ---------------- host ----------------
static const unsigned WOFF[13] = {0,2048,38912,112640,260096,555008,1144832,
                                  1734656,2914304,5273600,7632896,9992192,12351488};
static const int WO[13]  = {64,64,128,128,256,256,256,512,512,512,512,512,512};
static const int WKR[13] = {27,576,576,1152,1152,2304,2304,2304,4608,4608,4608,4608,4608};
static const int WKP[13] = {32,576,576,1152,1152,2304,2304,2304,4608,4608,4608,4608,4608};

struct Bufs {
    float *bufA, *bufB, *part, *vec1, *vec2;
    __nv_bfloat16 *colH, *colL, *wH, *wL;
};

// pool: 0 = none, 1 = fused maxpool (gemm epilogue if nsplit==1, else reduceK)
static void conv_mat(const Bufs& B, const float* in, float* out, int li,
                     int Cin, int Cout, int H, int tabBase, int nsplit, int pool) {
    int HW = H * H;
    int Ntot = BATCH * HW;
    int Kpad = WKP[li];
    int CB = Cin;
    while (CB > 1 && (Ntot / 256) * 9 * (Cin / CB) < 1024 && (CB & 1) == 0)
        CB >>= 1;
    if (CB > 16 && Ntot <= 8192) CB = 16;
    dim3 gi(Ntot / 256, 9, Cin / CB);
    im2col2<<<gi, 256>>>(in, B.colH, B.colL, Cin, HW, Ntot, tabBase, CB);
    dim3 gg(Ntot / 256, Cout / 64, nsplit);
    int gemmPool = (pool && nsplit == 1) ? 1 : 0;
    gemm_mma<<<gg, 256, SMEM_TOT>>>(B.colH, B.colL, B.wH + WOFF[li], B.wL + WOFF[li],
                                    out, B.part, Ntot, Kpad, Kpad / nsplit, Cout, HW, H, gemmPool);
    if (nsplit > 1) {
        int outs = pool ? (Cout * Ntot / 4) : (Cout * Ntot);
        reduceK<<<(outs + 255) / 256, 256>>>(B.part, out, Cout, Ntot, HW, H, nsplit, pool);
    }
}

extern "C" void kernel_launch(void* const* d_in, const int* in_sizes, int n_in,
                              void* d_out, int out_size) {
    const float* x = (const float*)d_in[0];
    const float* fc1w = (const float*)d_in[14];
    const float* fc1b = (const float*)d_in[15];
    const float* fc2w = (const float*)d_in[16];
    const float* fc2b = (const float*)d_in[17];
    const float* fc3w = (const float*)d_in[18];
    const float* fc3b = (const float*)d_in[19];
    float* outp = (float*)d_out;

    Bufs B;
    cudaGetSymbolAddress((void**)&B.bufA, g_bufA);
    cudaGetSymbolAddress((void**)&B.bufB, g_bufB);
    cudaGetSymbolAddress((void**)&B.part, g_part);
    cudaGetSymbolAddress((void**)&B.vec1, g_vec1);
    cudaGetSymbolAddress((void**)&B.vec2, g_vec2);
    cudaGetSymbolAddress((void**)&B.colH, g_colH);
    cudaGetSymbolAddress((void**)&B.colL, g_colL);
    cudaGetSymbolAddress((void**)&B.wH,  g_wH);
    cudaGetSymbolAddress((void**)&B.wL,  g_wL);

    cudaFuncSetAttribute(gemm_mma, cudaFuncAttributeMaxDynamicSharedMemorySize, SMEM_TOT);

    WParams P;
    for (int i = 0; i < 13; i++) {
        P.W[i] = (const float*)d_in[1 + i];
        P.O[i] = WO[i]; P.Kreal[i] = WKR[i]; P.Kpad[i] = WKP[i]; P.off[i] = WOFF[i];
    }

    prep_all<<<768, 256>>>();
    convW_all<<<dim3(512, 13), 256>>>(P, B.wH, B.wL);

    // block 1 (128x128): L1_2 pools in gemm epilogue
    conv_mat(B, x,      B.bufA, 0,  3,  64, 128, TB128, 1, 0);
    conv_mat(B, B.bufA, B.bufB, 1, 64,  64, 128, TB128, 1, 1);   // -> 64x64 pooled
    // block 2 (64x64)
    conv_mat(B, B.bufB, B.bufA, 2,  64, 128, 64, TB64, 1, 0);
    conv_mat(B, B.bufA, B.bufB, 3, 128, 128, 64, TB64, 1, 1);    // -> 32x32 pooled
    // block 3 (32x32)
    conv_mat(B, B.bufB, B.bufA, 4, 128, 256, 32, TB32, 2, 0);
    conv_mat(B, B.bufA, B.bufB, 5, 256, 256, 32, TB32, 2, 0);
    conv_mat(B, B.bufB, B.bufA, 6, 256, 256, 32, TB32, 2, 1);    // -> 16x16 pooled (reduceK)
    // block 4 (16x16)
    conv_mat(B, B.bufA, B.bufB, 7, 256, 512, 16, TB16, 4, 0);
    conv_mat(B, B.bufB, B.bufA, 8, 512, 512, 16, TB16, 4, 0);
    conv_mat(B, B.bufA, B.bufB, 9, 512, 512, 16, TB16, 4, 1);    // -> 8x8 pooled (reduceK)
    // block 5 (8x8)
    conv_mat(B, B.bufB, B.bufA, 10, 512, 512, 8, TB8, 16, 0);
    conv_mat(B, B.bufA, B.bufB, 11, 512, 512, 8, TB8, 16, 0);
    conv_mat(B, B.bufB, B.bufA, 12, 512, 512, 8, TB8, 16, 1);    // -> 4x4 pooled (reduceK)

    avgpool4<<<(BATCH*512 + 255) / 256, 256>>>(B.bufA, B.vec1);
    fc_kernel<<<(4096*32 + 255) / 256, 256>>>(B.vec1, fc1w, fc1b, B.vec2, 512, 4096, 1);
    fc_kernel<<<(4096*32 + 255) / 256, 256>>>(B.vec2, fc2w, fc2b, B.vec1, 4096, 4096, 1);
    fc_kernel<<<(30*32 + 255) / 256, 256>>>(B.vec1, fc3w, fc3b, outp, 4096, 30, 0);
}

// round 16
// speedup vs baseline: 1.1191x; 1.1191x over previous
#include <cuda_runtime.h>
#include <cuda_bf16.h>
#include <cstdint>

#define BATCH 8

// ---------------- scratch ----------------
__device__ float g_bufA[8u*64u*128u*128u];
__device__ float g_bufB[8u*64u*128u*128u];
__device__ __nv_bfloat16 g_colH[75497472u];
__device__ __nv_bfloat16 g_colL[75497472u];
__device__ __nv_bfloat16 g_wH[14710784u];
__device__ __nv_bfloat16 g_wL[14710784u];
__device__ float g_part[4194304u];
__device__ int4   g_tabI[196416];
__device__ float4 g_tabW[196416];
__device__ float g_vec1[8*4096];
__device__ float g_vec2[8*4096];

#define TB128 0
#define TB64  147456
#define TB32  184320
#define TB16  193536
#define TB8   195840

// ---------------- PTX helpers (family-common sm_80+) ----------------
__device__ __forceinline__ uint32_t s2u(const void* p) {
    uint32_t a;
    asm("{ .reg .u64 t; cvta.to.shared.u64 t, %1; cvt.u32.u64 %0, t; }" : "=r"(a) : "l"(p));
    return a;
}
#define CPA(dst, src) asm volatile("cp.async.cg.shared.global [%0], [%1], 16;" :: "r"(dst), "l"(src))
#define CPA_COMMIT()  asm volatile("cp.async.commit_group;" ::: "memory")
#define CPA_WAIT0()   asm volatile("cp.async.wait_group 0;" ::: "memory")
#define LDM4(r, addr) asm volatile("ldmatrix.sync.aligned.m8n8.x4.shared.b16 {%0,%1,%2,%3}, [%4];" \
    : "=r"((r)[0]), "=r"((r)[1]), "=r"((r)[2]), "=r"((r)[3]) : "r"(addr))
#define LDM4T(r, addr) asm volatile("ldmatrix.sync.aligned.m8n8.x4.trans.shared.b16 {%0,%1,%2,%3}, [%4];" \
    : "=r"((r)[0]), "=r"((r)[1]), "=r"((r)[2]), "=r"((r)[3]) : "r"(addr))
#define MMA(d, a, b) asm volatile( \
    "mma.sync.aligned.m16n8k16.row.col.f32.bf16.bf16.f32 {%0,%1,%2,%3},{%4,%5,%6,%7},{%8,%9},{%0,%1,%2,%3};" \
    : "+f"((d)[0]), "+f"((d)[1]), "+f"((d)[2]), "+f"((d)[3]) \
    : "r"((a)[0]), "r"((a)[1]), "r"((a)[2]), "r"((a)[3]), "r"((b)[0]), "r"((b)[1]))

// ---------------- tab build ----------------
__device__ __forceinline__ void tab_one(int t, int H, int base) {
    int HW = H * H;
    if (t >= HW * 9) return;
    int k = t % 9, pos = t / 9;
    int y = pos / H, x = pos % H;

    float cc = 0.5f * (float)H - 0.5f;
    float th = atan2f((float)x - cc, (float)y - cc);
    if (th < 0.f) th += 6.28318530717958647692f;
    th = rintf(th * 10000.0f) / 10000.0f;

    int ky = k / 3, kx = k % 3;
    float offy = 0.f, offx = 0.f;
    if (k != 4) {
        int m = (k < 4) ? k : k - 1;
        float ang = th + (float)(3.14159265358979323846 * 0.25 * (double)m);
        offy = cosf(ang) + (float)(1 - ky);
        offx = sinf(ang) + (float)(1 - kx);
    }
    float py = (float)(y - 1 + ky) + offy;
    float px = (float)(x - 1 + kx) + offx;
    float y0 = floorf(py), x0 = floorf(px);
    float fy = py - y0, fx = px - x0;
    float Hm = (float)(H - 1);

    float ys[2] = {y0, y0 + 1.f};
    float xs[2] = {x0, x0 + 1.f};
    float wy[2] = {1.f - fy, fy};
    float wx[2] = {1.f - fx, fx};

    int ids[4]; float ws[4]; int q = 0;
    #pragma unroll
    for (int iy = 0; iy < 2; iy++) {
        #pragma unroll
        for (int ix = 0; ix < 2; ix++) {
            float yf = ys[iy], xf = xs[ix];
            bool v = (yf >= 0.f) && (yf <= Hm) && (xf >= 0.f) && (xf <= Hm);
            int yi = (int)fminf(fmaxf(yf, 0.f), Hm);
            int xi = (int)fminf(fmaxf(xf, 0.f), Hm);
            ids[q] = yi * H + xi;
            ws[q]  = v ? (wy[iy] * wx[ix]) : 0.f;
            q++;
        }
    }
    g_tabI[base + t] = make_int4(ids[0], ids[1], ids[2], ids[3]);
    g_tabW[base + t] = make_float4(ws[0], ws[1], ws[2], ws[3]);
}

// ---------------- combined prep: y==13 -> tabs, else weight layer y ----------------
struct WParams {
    const float* W[13];
    int O[13]; int Kreal[13]; int Kpad[13]; unsigned off[13];
};
__global__ void prep_combo(WParams P, __nv_bfloat16* __restrict__ wH, __nv_bfloat16* __restrict__ wL) {
    int bx = blockIdx.x, layer = blockIdx.y, t = threadIdx.x;
    if (layer == 13) {
        if      (bx < 576) tab_one((bx      ) * 256 + t, 128, TB128);
        else if (bx < 720) tab_one((bx - 576) * 256 + t,  64, TB64);
        else if (bx < 756) tab_one((bx - 720) * 256 + t,  32, TB32);
        else if (bx < 765) tab_one((bx - 756) * 256 + t,  16, TB16);
        else if (bx < 768) tab_one((bx - 765) * 256 + t,   8, TB8);
        return;
    }
    int Kr = P.Kreal[layer], Kp = P.Kpad[layer];
    int total = P.O[layer] * Kp;
    const float* W = P.W[layer];
    unsigned off = P.off[layer];
    for (int u = bx * 256 + t; u < total; u += gridDim.x * 256) {
        int o = u / Kp, k = u - o * Kp;
        float w = (k < Kr) ? W[(size_t)o * Kr + k] : 0.f;
        __nv_bfloat16 h = __float2bfloat16(w);
        wH[off + u] = h;
        wL[off + u] = __float2bfloat16(w - __bfloat162float(h));
    }
}

// ---------------- im2col: 2 positions/thread, packed u32 stores, channel-parallel ----------------
__global__ void im2col2(const float* __restrict__ x, __nv_bfloat16* __restrict__ colH,
                        __nv_bfloat16* __restrict__ colL, int Cin, int HW, int Ntot,
                        int tabBase, int CB) {
    int n0 = (blockIdx.x * blockDim.x + threadIdx.x) * 2;
    int tap = blockIdx.y;
    int c0 = blockIdx.z * CB;
    int pos = n0 % HW, b = n0 / HW;        // HW even -> n0,n0+1 same image
    int4   id0 = g_tabI[tabBase + pos * 9 + tap];
    float4 w0  = g_tabW[tabBase + pos * 9 + tap];
    int4   id1 = g_tabI[tabBase + (pos + 1) * 9 + tap];
    float4 w1  = g_tabW[tabBase + (pos + 1) * 9 + tap];
    const float* xb = x + ((size_t)b * Cin + c0) * HW;
    size_t cstep = (size_t)9 * Ntot;
    __nv_bfloat16* pH = colH + ((size_t)c0 * 9 + tap) * Ntot + n0;
    __nv_bfloat16* pL = colL + ((size_t)c0 * 9 + tap) * Ntot + n0;
    for (int c = 0; c < CB; c++) {
        const float* xc = xb + (size_t)c * HW;
        float v0 = xc[id0.x] * w0.x + xc[id0.y] * w0.y + xc[id0.z] * w0.z + xc[id0.w] * w0.w;
        float v1 = xc[id1.x] * w1.x + xc[id1.y] * w1.y + xc[id1.z] * w1.z + xc[id1.w] * w1.w;
        __nv_bfloat16 h0 = __float2bfloat16(v0);
        __nv_bfloat16 h1 = __float2bfloat16(v1);
        __nv_bfloat16 l0 = __float2bfloat16(v0 - __bfloat162float(h0));
        __nv_bfloat16 l1 = __float2bfloat16(v1 - __bfloat162float(h1));
        uint32_t ph = (uint32_t)*(uint16_t*)&h0 | ((uint32_t)*(uint16_t*)&h1 << 16);
        uint32_t pl = (uint32_t)*(uint16_t*)&l0 | ((uint32_t)*(uint16_t*)&l1 << 16);
        *(uint32_t*)(pH + c * cstep) = ph;
        *(uint32_t*)(pL + c * cstep) = pl;
    }
}

// ---------------- HMMA GEMM 256x64x32, 2 CTAs/SM, optional fused ReLU+maxpool ----------------
#define RSA 264
#define RSB 40
#define OF_AL 16896
#define OF_B  33792
#define OF_BL 5120
#define STAGE_B 44032
#define SMEM_TOT 88064
#define PRS 66
__global__ void __launch_bounds__(256, 2) gemm_mma(
    const __nv_bfloat16* __restrict__ AH, const __nv_bfloat16* __restrict__ AL,
    const __nv_bfloat16* __restrict__ WH, const __nv_bfloat16* __restrict__ WL,
    float* __restrict__ out, float* __restrict__ part,
    int Ntot, int Kpad, int chunkK, int Cout, int HW, int H, int doPool) {
    extern __shared__ char smem[];
    uint32_t sb0 = s2u(smem);
    int tid = threadIdx.x, l = tid & 31, wid = tid >> 5;
    int wm = wid & 3, wn = wid >> 2;
    int bn = blockIdx.x * 256, bo = blockIdx.y * 64;
    int kStart = blockIdx.z * chunkK;
    int nk = chunkK >> 5;

    float acc[4][4][4];
    #pragma unroll
    for (int i = 0; i < 4; i++)
        #pragma unroll
        for (int j = 0; j < 4; j++)
            #pragma unroll
            for (int q = 0; q < 4; q++) acc[i][j][q] = 0.f;

    auto load_stage = [&](int st, int k0) {
        uint32_t sb = sb0 + st * STAGE_B;
        #pragma unroll
        for (int i = 0; i < 8; i++) {
            int u = tid + i * 256;
            int plane = u >> 10, rem = u & 1023;
            int krow = rem >> 5, c = rem & 31;
            const __nv_bfloat16* src = (plane ? AL : AH) + (size_t)(k0 + krow) * Ntot + bn + c * 8;
            uint32_t dst = sb + plane * OF_AL + (uint32_t)(krow * RSA + c * 8) * 2;
            CPA(dst, src);
        }
        #pragma unroll
        for (int i = 0; i < 2; i++) {
            int u = tid + i * 256;
            int plane = u >> 8, rem = u & 255;
            int row = rem >> 2, c = rem & 3;
            const __nv_bfloat16* src = (plane ? WL : WH) + (size_t)(bo + row) * Kpad + k0 + c * 8;
            uint32_t dst = sb + OF_B + plane * OF_BL + (uint32_t)(row * RSB + c * 8) * 2;
            CPA(dst, src);
        }
        CPA_COMMIT();
    };

    load_stage(0, kStart);

    int krow = (l & 7) + ((l & 16) >> 1);
    int mcol = (l & 8);
    int browB = (l & 7) + ((l >> 4) << 3);
    int bcol  = ((l >> 3) & 1) * 8;

    for (int it = 0; it < nk; it++) {
        CPA_WAIT0();
        __syncthreads();
        if (it + 1 < nk) load_stage((it + 1) & 1, kStart + (it + 1) * 32);

        uint32_t base = sb0 + (it & 1) * STAGE_B;
        #pragma unroll
        for (int ks = 0; ks < 2; ks++) {
            uint32_t aH[4][4], aL[4][4], bH[4][2], bL[4][2];
            #pragma unroll
            for (int mi = 0; mi < 4; mi++) {
                uint32_t off = (uint32_t)((ks * 16 + krow) * RSA + wm * 64 + mi * 16 + mcol) * 2;
                LDM4T(aH[mi], base + off);
                LDM4T(aL[mi], base + OF_AL + off);
            }
            #pragma unroll
            for (int j = 0; j < 2; j++) {
                int row = wn * 32 + j * 16 + browB;
                uint32_t off = OF_B + (uint32_t)(row * RSB + ks * 16 + bcol) * 2;
                uint32_t r[4];
                LDM4(r, base + off);
                bH[2*j][0] = r[0]; bH[2*j][1] = r[1]; bH[2*j+1][0] = r[2]; bH[2*j+1][1] = r[3];
                LDM4(r, base + off + OF_BL);
                bL[2*j][0] = r[0]; bL[2*j][1] = r[1]; bL[2*j+1][0] = r[2]; bL[2*j+1][1] = r[3];
            }
            // reordered: all hh, then all hl, then all lh (same math, longer RAW distance)
            #pragma unroll
            for (int mi = 0; mi < 4; mi++)
                #pragma unroll
                for (int nf = 0; nf < 4; nf++)
                    MMA(acc[mi][nf], aH[mi], bH[nf]);
            #pragma unroll
            for (int mi = 0; mi < 4; mi++)
                #pragma unroll
                for (int nf = 0; nf < 4; nf++)
                    MMA(acc[mi][nf], aH[mi], bL[nf]);
            #pragma unroll
            for (int mi = 0; mi < 4; mi++)
                #pragma unroll
                for (int nf = 0; nf < 4; nf++)
                    MMA(acc[mi][nf], aL[mi], bH[nf]);
        }
        __syncthreads();
    }

    if (doPool) {
        float* st = (float*)smem;
        #pragma unroll
        for (int mi = 0; mi < 4; mi++)
            #pragma unroll
            for (int nf = 0; nf < 4; nf++) {
                int pl = wm * 64 + mi * 16 + (l >> 2);
                int cl = wn * 32 + nf * 8 + 2 * (l & 3);
                float* d = acc[mi][nf];
                st[pl * PRS + cl]           = d[0];
                st[pl * PRS + cl + 1]       = d[1];
                st[(pl + 8) * PRS + cl]     = d[2];
                st[(pl + 8) * PRS + cl + 1] = d[3];
            }
        __syncthreads();
        int b0 = bn / HW;
        int HWo = HW >> 2, Ho2 = H >> 1;
        int pbase = (bn % HW) >> 2;
        #pragma unroll
        for (int i = 0; i < 16; i++) {
            int v = tid + i * 256;
            int col = v >> 6, pp = v & 63;
            int yp = pp / Ho2, xp = pp - yp * Ho2;
            int pl = 2 * yp * H + 2 * xp;
            float m = fmaxf(fmaxf(st[pl * PRS + col], st[(pl + 1) * PRS + col]),
                            fmaxf(st[(pl + H) * PRS + col], st[(pl + H + 1) * PRS + col]));
            out[((size_t)b0 * Cout + bo + col) * HWo + pbase + pp] = fmaxf(m, 0.f);
        }
        return;
    }

    bool dosplit = (gridDim.z > 1);
    #pragma unroll
    for (int mi = 0; mi < 4; mi++)
        #pragma unroll
        for (int nf = 0; nf < 4; nf++) {
            int row0 = bn + wm * 64 + mi * 16 + (l >> 2);
            int col0 = bo + wn * 32 + nf * 8 + 2 * (l & 3);
            float* d = acc[mi][nf];
            if (dosplit) {
                size_t zb = (size_t)blockIdx.z * Cout;
                part[(zb + col0)     * Ntot + row0]     = d[0];
                part[(zb + col0 + 1) * Ntot + row0]     = d[1];
                part[(zb + col0)     * Ntot + row0 + 8] = d[2];
                part[(zb + col0 + 1) * Ntot + row0 + 8] = d[3];
            } else {
                int b0 = row0 / HW, p0 = row0 % HW;
                int r1 = row0 + 8;
                int b1 = r1 / HW, p1 = r1 % HW;
                out[((size_t)b0 * Cout + col0)     * HW + p0] = fmaxf(d[0], 0.f);
                out[((size_t)b0 * Cout + col0 + 1) * HW + p0] = fmaxf(d[1], 0.f);
                out[((size_t)b1 * Cout + col0)     * HW + p1] = fmaxf(d[2], 0.f);
                out[((size_t)b1 * Cout + col0 + 1) * HW + p1] = fmaxf(d[3], 0.f);
            }
        }
}

// ---------------- split-K reduce + ReLU (optional fused maxpool) ----------------
__global__ void reduceK(const float* __restrict__ part, float* __restrict__ out,
                        int Cout, int N, int HW, int H, int nslab, int doPool) {
    int t = blockIdx.x * blockDim.x + threadIdx.x;
    if (!doPool) {
        if (t >= Cout * N) return;
        int o = t / N, n = t % N;
        float s = 0.f;
        for (int z = 0; z < nslab; z++)
            s += part[((size_t)z * Cout + o) * N + n];
        int b = n / HW, pos = n % HW;
        out[((size_t)b * Cout + o) * HW + pos] = fmaxf(s, 0.f);
    } else {
        int N4 = N >> 2;
        if (t >= Cout * N4) return;
        int o = t / N4, r = t - o * N4;
        int HWo = HW >> 2, Ho2 = H >> 1;
        int b = r / HWo, pp = r - b * HWo;
        int yp = pp / Ho2, xp = pp - yp * Ho2;
        int n00 = b * HW + 2 * yp * H + 2 * xp;
        float s00 = 0.f, s01 = 0.f, s10 = 0.f, s11 = 0.f;
        for (int z = 0; z < nslab; z++) {
            const float* p = part + ((size_t)z * Cout + o) * N + n00;
            s00 += p[0]; s01 += p[1]; s10 += p[H]; s11 += p[H + 1];
        }
        float m = fmaxf(fmaxf(s00, s01), fmaxf(s10, s11));
        out[((size_t)b * Cout + o) * HWo + pp] = fmaxf(m, 0.f);
    }
}

// ---------------- avgpool / FC ----------------
__global__ void avgpool4(const float* __restrict__ in, float* __restrict__ out) {
    int t = blockIdx.x * blockDim.x + threadIdx.x;
    if (t >= BATCH * 512) return;
    const float* p = in + (size_t)t * 16;
    float s = 0.f;
    #pragma unroll
    for (int i = 0; i < 16; i++) s += p[i];
    out[t] = s * (1.f / 16.f);
}

__global__ void fc_kernel(const float* __restrict__ v, const float* __restrict__ Wf,
                          const float* __restrict__ bias, float* __restrict__ out,
                          int In, int Out, int doRelu) {
    int warp = (blockIdx.x * blockDim.x + threadIdx.x) >> 5;
    int lane = threadIdx.x & 31;
    if (warp >= Out) return;
    const float* wrow = Wf + (size_t)warp * In;
    float acc[BATCH];
    #pragma unroll
    for (int b = 0; b < BATCH; b++) acc[b] = 0.f;
    for (int i = lane; i < In; i += 32) {
        float wv = wrow[i];
        #pragma unroll
        for (int b = 0; b < BATCH; b++)
            acc[b] = fmaf(wv, v[b * In + i], acc[b]);
    }
    #pragma unroll
    for (int b = 0; b < BATCH; b++) {
        #pragma unroll
        for (int off = 16; off; off >>= 1)
            acc[b] += __shfl_xor_sync(0xffffffffu, acc[b], off);
    }
    if (lane == 0) {
        float bi = bias[warp];
        #pragma unroll
        for (int b = 0; b < BATCH; b++) {
            float r = acc[b] + bi;
            if (doRelu) r = fmaxf(r, 0.f);
            out[b * Out + warp] = r;
        }
    }
}

// ---------------- host ----------------
static const unsigned WOFF[13] = {0,2048,38912,112640,260096,555008,1144832,
                                  1734656,2914304,5273600,7632896,9992192,12351488};
static const int WO[13]  = {64,64,128,128,256,256,256,512,512,512,512,512,512};
static const int WKR[13] = {27,576,576,1152,1152,2304,2304,2304,4608,4608,4608,4608,4608};
static const int WKP[13] = {32,576,576,1152,1152,2304,2304,2304,4608,4608,4608,4608,4608};

struct Bufs {
    float *bufA, *bufB, *part, *vec1, *vec2;
    __nv_bfloat16 *colH, *colL, *wH, *wL;
};

static void conv_mat(const Bufs& B, const float* in, float* out, int li,
                     int Cin, int Cout, int H, int tabBase, int nsplit, int pool) {
    int HW = H * H;
    int Ntot = BATCH * HW;
    int Kpad = WKP[li];
    int nBlk = Ntot / 512;                 // 2 positions per thread
    int CB = Cin;
    while (CB > 1 && nBlk * 9 * (Cin / CB) < 1024 && (CB & 1) == 0)
        CB >>= 1;
    if (CB > 16 && Ntot <= 8192) CB = 16;
    dim3 gi(nBlk, 9, Cin / CB);
    im2col2<<<gi, 256>>>(in, B.colH, B.colL, Cin, HW, Ntot, tabBase, CB);
    dim3 gg(Ntot / 256, Cout / 64, nsplit);
    int gemmPool = (pool && nsplit == 1) ? 1 : 0;
    gemm_mma<<<gg, 256, SMEM_TOT>>>(B.colH, B.colL, B.wH + WOFF[li], B.wL + WOFF[li],
                                    out, B.part, Ntot, Kpad, Kpad / nsplit, Cout, HW, H, gemmPool);
    if (nsplit > 1) {
        int outs = pool ? (Cout * Ntot / 4) : (Cout * Ntot);
        reduceK<<<(outs + 255) / 256, 256>>>(B.part, out, Cout, Ntot, HW, H, nsplit, pool);
    }
}

extern "C" void kernel_launch(void* const* d_in, const int* in_sizes, int n_in,
                              void* d_out, int out_size) {
    const float* x = (const float*)d_in[0];
    const float* fc1w = (const float*)d_in[14];
    const float* fc1b = (const float*)d_in[15];
    const float* fc2w = (const float*)d_in[16];
    const float* fc2b = (const float*)d_in[17];
    const float* fc3w = (const float*)d_in[18];
    const float* fc3b = (const float*)d_in[19];
    float* outp = (float*)d_out;

    Bufs B;
    cudaGetSymbolAddress((void**)&B.bufA, g_bufA);
    cudaGetSymbolAddress((void**)&B.bufB, g_bufB);
    cudaGetSymbolAddress((void**)&B.part, g_part);
    cudaGetSymbolAddress((void**)&B.vec1, g_vec1);
    cudaGetSymbolAddress((void**)&B.vec2, g_vec2);
    cudaGetSymbolAddress((void**)&B.colH, g_colH);
    cudaGetSymbolAddress((void**)&B.colL, g_colL);
    cudaGetSymbolAddress((void**)&B.wH,  g_wH);
    cudaGetSymbolAddress((void**)&B.wL,  g_wL);

    cudaFuncSetAttribute(gemm_mma, cudaFuncAttributeMaxDynamicSharedMemorySize, SMEM_TOT);

    WParams P;
    for (int i = 0; i < 13; i++) {
        P.W[i] = (const float*)d_in[1 + i];
        P.O[i] = WO[i]; P.Kreal[i] = WKR[i]; P.Kpad[i] = WKP[i]; P.off[i] = WOFF[i];
    }

    // 1: prep_combo; 2: L1_1 im2col; 3: L1_1 gemm; 4: L1_2 im2col (profiled)
    prep_combo<<<dim3(768, 14), 256>>>(P, B.wH, B.wL);

    conv_mat(B, x,      B.bufA, 0,  3,  64, 128, TB128, 1, 0);
    conv_mat(B, B.bufA, B.bufB, 1, 64,  64, 128, TB128, 1, 1);   // -> 64x64 pooled
    conv_mat(B, B.bufB, B.bufA, 2,  64, 128, 64, TB64, 1, 0);
    conv_mat(B, B.bufA, B.bufB, 3, 128, 128, 64, TB64, 1, 1);    // -> 32x32 pooled
    conv_mat(B, B.bufB, B.bufA, 4, 128, 256, 32, TB32, 2, 0);
    conv_mat(B, B.bufA, B.bufB, 5, 256, 256, 32, TB32, 2, 0);
    conv_mat(B, B.bufB, B.bufA, 6, 256, 256, 32, TB32, 2, 1);    // -> 16x16 pooled
    conv_mat(B, B.bufA, B.bufB, 7, 256, 512, 16, TB16, 4, 0);
    conv_mat(B, B.bufB, B.bufA, 8, 512, 512, 16, TB16, 4, 0);
    conv_mat(B, B.bufA, B.bufB, 9, 512, 512, 16, TB16, 4, 1);    // -> 8x8 pooled
    conv_mat(B, B.bufB, B.bufA, 10, 512, 512, 8, TB8, 16, 0);
    conv_mat(B, B.bufA, B.bufB, 11, 512, 512, 8, TB8, 16, 0);
    conv_mat(B, B.bufB, B.bufA, 12, 512, 512, 8, TB8, 16, 1);    // -> 4x4 pooled

    avgpool4<<<(BATCH*512 + 255) / 256, 256>>>(B.bufA, B.vec1);
    fc_kernel<<<(4096*32 + 255) / 256, 256>>>(B.vec1, fc1w, fc1b, B.vec2, 512, 4096, 1);
    fc_kernel<<<(4096*32 + 255) / 256, 256>>>(B.vec2, fc2w, fc2b, B.vec1, 4096, 4096, 1);
    fc_kernel<<<(30*32 + 255) / 256, 256>>>(B.vec1, fc3w, fc3b, outp, 4096, 30, 0);
}